// round 5
// baseline (speedup 1.0000x reference)
#include <cuda_runtime.h>
#include <cstdint>

#define N_NODES 2708
#define INS     1433
#define OUTS    64
#define M_MECH  8
#define HID     64
#define LEAK    0.2f
#define NW      85   // ceil(2708/32)

typedef unsigned long long ull;

// ---------------- device scratch (no allocation allowed) ----------------
__device__ unsigned g_adj[N_NODES * NW];
__device__ float g_h[(size_t)M_MECH * N_NODES * OUTS];   // FiLM'd projections
__device__ float g_h1[(size_t)N_NODES * HID];            // conditioner hidden
__device__ float g_gamma[M_MECH * N_NODES];
__device__ float g_beta[M_MECH * N_NODES];
__device__ float g_es[M_MECH * N_NODES];
__device__ float g_ed[M_MECH * N_NODES];

// ---------------- f32x2 helpers (sm_103a packed FP32) ----------------
__device__ __forceinline__ ull pk2(float a, float b) {
    ull r; asm("mov.b64 %0, {%1, %2};" : "=l"(r) : "f"(a), "f"(b)); return r;
}
__device__ __forceinline__ float2 upk2(ull v) {
    float2 r; asm("mov.b64 {%0, %1}, %2;" : "=f"(r.x), "=f"(r.y) : "l"(v)); return r;
}
__device__ __forceinline__ ull ffma2(ull a, ull b, ull c) {
    ull d; asm("fma.rn.f32x2 %0, %1, %2, %3;" : "=l"(d) : "l"(a), "l"(b), "l"(c)); return d;
}

// ---------------- K1: bit-pack adjacency ----------------
// works for adj serialized as int32 (0/1) OR float32 (0.0/1.0): nonzero word = edge
__global__ void k_pack(const unsigned* __restrict__ adj) {
    int i = blockIdx.x;
    int lane = threadIdx.x & 31, w0 = threadIdx.x >> 5;
    for (int w = w0; w < NW; w += 4) {
        int j = w * 32 + lane;
        bool p = (j < N_NODES) && (adj[(size_t)i * N_NODES + j] != 0u);
        unsigned mask = __ballot_sync(0xFFFFFFFFu, p);
        if (lane == 0) g_adj[i * NW + w] = mask;
    }
}

// ---------------- K2: fused big GEMM ----------------
// C[2708, 9*64]: block gy<8 -> h_raw for mechanism gy; gy==8 -> relu(x@Wc1+bc1)
// 64x64 tile, K-chunk 16, 256 threads, 4x4 microtile with FFMA2
__global__ void k_gemm(const float* __restrict__ x, const float* __restrict__ W,
                       const float* __restrict__ Wc1, const float* __restrict__ bc1) {
    __shared__ float xs[16][68];  // transposed: xs[k][row]
    __shared__ float bs[16][64];  // bs[k][col]

    int n0 = blockIdx.x * 64;
    int gy = blockIdx.y;
    const float* B = (gy < M_MECH) ? (W + (size_t)gy * INS * OUTS) : Wc1;

    int t = threadIdx.x;
    int trow = t >> 4, tcol = t & 15;

    ull acc[8];
#pragma unroll
    for (int i = 0; i < 8; i++) acc[i] = 0ull;

    for (int k0 = 0; k0 < INS; k0 += 16) {
#pragma unroll
        for (int i = 0; i < 4; i++) {
            int e = t + 256 * i;
            int row = e >> 4, kk = e & 15;
            int gr = n0 + row, gk = k0 + kk;
            float v = (gr < N_NODES && gk < INS) ? x[(size_t)gr * INS + gk] : 0.f;
            xs[kk][row] = v;
        }
#pragma unroll
        for (int i = 0; i < 4; i++) {
            int e = t + 256 * i;
            int kk = e >> 6, o = e & 63;
            int gk = k0 + kk;
            float v = (gk < INS) ? B[(size_t)gk * 64 + o] : 0.f;
            bs[kk][o] = v;
        }
        __syncthreads();
#pragma unroll
        for (int kk = 0; kk < 16; kk++) {
            float4 a4 = *(const float4*)&xs[kk][trow * 4];
            float4 b4 = *(const float4*)&bs[kk][tcol * 4];
            ull b01 = pk2(b4.x, b4.y), b23 = pk2(b4.z, b4.w);
            float av[4] = {a4.x, a4.y, a4.z, a4.w};
#pragma unroll
            for (int i = 0; i < 4; i++) {
                ull ai = pk2(av[i], av[i]);
                acc[i * 2]     = ffma2(ai, b01, acc[i * 2]);
                acc[i * 2 + 1] = ffma2(ai, b23, acc[i * 2 + 1]);
            }
        }
        __syncthreads();
    }

#pragma unroll
    for (int i = 0; i < 4; i++) {
        int n = n0 + trow * 4 + i;
        if (n >= N_NODES) continue;
        float2 c01 = upk2(acc[i * 2]);
        float2 c23 = upk2(acc[i * 2 + 1]);
        int oc = tcol * 4;
        if (gy < M_MECH) {
            float4 v = make_float4(c01.x, c01.y, c23.x, c23.y);
            *(float4*)&g_h[((size_t)gy * N_NODES + n) * 64 + oc] = v;
        } else {
            float4 v = make_float4(fmaxf(c01.x + bc1[oc], 0.f),
                                   fmaxf(c01.y + bc1[oc + 1], 0.f),
                                   fmaxf(c23.x + bc1[oc + 2], 0.f),
                                   fmaxf(c23.y + bc1[oc + 3], 0.f));
            *(float4*)&g_h1[(size_t)n * 64 + oc] = v;
        }
    }
}

// ---------------- K3: conditioner output -> gamma/beta ----------------
// warp per node: cond[n, 0:16] = h1[n,:] @ Wc2 + bc2 ; gamma = cols 0..7, beta = 8..15
__global__ void k_cond2(const float* __restrict__ Wc2, const float* __restrict__ bc2) {
    int n = blockIdx.x * 8 + (threadIdx.x >> 5);
    int lane = threadIdx.x & 31;
    if (n >= N_NODES) return;
    float v0 = g_h1[(size_t)n * 64 + lane];
    float v1 = g_h1[(size_t)n * 64 + 32 + lane];
    float s = (lane < 16) ? bc2[lane] : 0.f;
#pragma unroll
    for (int k = 0; k < 64; k++) {
        float hv = __shfl_sync(0xFFFFFFFFu, (k < 32) ? v0 : v1, k & 31);
        float w = (lane < 16) ? Wc2[k * 16 + lane] : 0.f;
        s = fmaf(hv, w, s);
    }
    if (lane < 8)       g_gamma[lane * N_NODES + n] = s;
    else if (lane < 16) g_beta[(lane - 8) * N_NODES + n] = s;
}

// ---------------- K4: FiLM in-place + e_src/e_dst ----------------
__global__ void k_film(const float* __restrict__ a_src, const float* __restrict__ a_dst) {
    int m = blockIdx.y;
    int n = blockIdx.x * 8 + (threadIdx.x >> 5);
    int lane = threadIdx.x & 31;
    if (n >= N_NODES) return;
    float g = g_gamma[m * N_NODES + n], b = g_beta[m * N_NODES + n];
    size_t base = ((size_t)m * N_NODES + n) * 64;
    float h0 = g_h[base + lane], h1 = g_h[base + 32 + lane];
    h0 = fmaf(g, h0, b);
    h1 = fmaf(g, h1, b);
    g_h[base + lane] = h0;
    g_h[base + 32 + lane] = h1;
    float es = h0 * a_src[m * 64 + lane] + h1 * a_src[m * 64 + 32 + lane];
    float ed = h0 * a_dst[m * 64 + lane] + h1 * a_dst[m * 64 + 32 + lane];
#pragma unroll
    for (int off = 16; off; off >>= 1) {
        es += __shfl_xor_sync(0xFFFFFFFFu, es, off);
        ed += __shfl_xor_sync(0xFFFFFFFFu, ed, off);
    }
    if (lane == 0) { g_es[m * N_NODES + n] = es; g_ed[m * N_NODES + n] = ed; }
}

// ---------------- K5: masked softmax + aggregation (flash-style) ----------------
// block = (m, 32-row tile), 256 threads. Dynamic smem kept < 48KB so no
// cudaFuncSetAttribute is needed (pure kernel launches in kernel_launch).
#define AR 32                                 // rows per block
#define SMEM_ATTN_WORDS (2720 + AR*NW + 4096 + AR*65 + AR + AR + AR)
#define SMEM_ATTN_BYTES (SMEM_ATTN_WORDS * 4)  // = 46848 bytes

__global__ void k_attn(float* __restrict__ out) {
    extern __shared__ char smem_raw[];
    float*    ed_s = (float*)smem_raw;            // [2720]
    unsigned* adjs = (unsigned*)(ed_s + 2720);    // [AR*85]
    float*    hs   = (float*)(adjs + AR * NW);    // [64*64]
    float*    ws   = hs + 4096;                   // [AR*65] padded stride
    float*    es_s = ws + AR * 65;                // [AR]
    float*    maxs = es_s + AR;                   // [AR]
    float*    invs = maxs + AR;                   // [AR]

    int m = blockIdx.y;
    int n0 = blockIdx.x * AR;
    int t = threadIdx.x, lane = t & 31, wid = t >> 5;

    for (int j = t; j < N_NODES; j += 256) ed_s[j] = g_ed[m * N_NODES + j];
    if (t < AR) {
        int n = n0 + t;
        es_s[t] = (n < N_NODES) ? g_es[m * N_NODES + n] : 0.f;
    }
    for (int e = t; e < AR * NW; e += 256) {
        int r = e / NW, w = e % NW;
        int n = n0 + r;
        adjs[e] = (n < N_NODES) ? g_adj[n * NW + w] : 0u;
    }
    __syncthreads();

    // pass 1: online max + sumexp per row (warp per row)
    for (int r = wid; r < AR; r += 8) {
        float es = es_s[r];
        float mx = -1e30f, sm = 0.f;
        for (int j = lane; j < N_NODES; j += 32) {
            unsigned bit = (adjs[r * NW + (j >> 5)] >> (j & 31)) & 1u;
            if (bit) {
                float v = es + ed_s[j];
                v = (v > 0.f) ? v : LEAK * v;
                if (v > mx) { sm = sm * __expf(mx - v) + 1.f; mx = v; }
                else        { sm += __expf(v - mx); }
            }
        }
#pragma unroll
        for (int off = 16; off; off >>= 1) {
            float mo = __shfl_xor_sync(0xFFFFFFFFu, mx, off);
            float so = __shfl_xor_sync(0xFFFFFFFFu, sm, off);
            float mn = fmaxf(mx, mo);
            sm = sm * __expf(mx - mn) + so * __expf(mo - mn);
            mx = mn;
        }
        if (lane == 0) {
            maxs[r] = mx;
            invs[r] = (sm > 0.f) ? 1.f / sm : 0.f;
        }
    }
    __syncthreads();

    // pass 2: weighted accumulate over j-tiles of 64
    // 256 threads: 8 threads per row, each owns 8 output features (4 f32x2 accs)
    int r = t >> 3, og = t & 7, ob = og * 8;
    ull acc[4];
#pragma unroll
    for (int i = 0; i < 4; i++) acc[i] = 0ull;

    for (int jt = 0; jt < N_NODES; jt += 64) {
        const float* hsrc = g_h + ((size_t)m * N_NODES + jt) * 64;
        int jrem = N_NODES - jt;
#pragma unroll
        for (int i = 0; i < 4; i++) {
            int e4 = t + 256 * i;               // 1024 float4s = 64x64 tile
            int jj = e4 >> 4, oc = (e4 & 15) * 4;
            float4 v = (jj < jrem) ? *(const float4*)&hsrc[(size_t)jj * 64 + oc]
                                   : make_float4(0.f, 0.f, 0.f, 0.f);
            *(float4*)&hs[jj * 64 + oc] = v;
        }
#pragma unroll
        for (int i = 0; i < 8; i++) {
            int e = t + 256 * i;                // AR*64 = 2048 entries
            int rr = e >> 6, jl = e & 63;
            int j = jt + jl;
            float w = 0.f;
            if (j < N_NODES) {
                unsigned bit = (adjs[rr * NW + (j >> 5)] >> (j & 31)) & 1u;
                if (bit) {
                    float v = es_s[rr] + ed_s[j];
                    v = (v > 0.f) ? v : LEAK * v;
                    w = __expf(v - maxs[rr]);
                }
            }
            ws[rr * 65 + jl] = w;
        }
        __syncthreads();
#pragma unroll 8
        for (int jj = 0; jj < 64; jj++) {
            float w = ws[r * 65 + jj];
            ull w2 = pk2(w, w);
            const ull* hp = (const ull*)&hs[jj * 64 + ob];
            ulonglong2 p0 = *(const ulonglong2*)(hp);
            ulonglong2 p1 = *(const ulonglong2*)(hp + 2);
            acc[0] = ffma2(w2, p0.x, acc[0]);
            acc[1] = ffma2(w2, p0.y, acc[1]);
            acc[2] = ffma2(w2, p1.x, acc[2]);
            acc[3] = ffma2(w2, p1.y, acc[3]);
        }
        __syncthreads();
    }

    int n = n0 + r;
    if (n < N_NODES) {
        float inv = invs[r];
        float o8[8];
#pragma unroll
        for (int i = 0; i < 4; i++) {
            float2 f = upk2(acc[i]);
            o8[2 * i]     = f.x * inv;
            o8[2 * i + 1] = f.y * inv;
        }
        float* dst = out + (size_t)n * (M_MECH * OUTS) + m * 64 + ob;
        *(float4*)(dst)     = make_float4(o8[0], o8[1], o8[2], o8[3]);
        *(float4*)(dst + 4) = make_float4(o8[4], o8[5], o8[6], o8[7]);
    }
}

// ---------------- launch ----------------
extern "C" void kernel_launch(void* const* d_in, const int* in_sizes, int n_in,
                              void* d_out, int out_size) {
    const float*    x     = (const float*)d_in[0];
    const unsigned* adj   = (const unsigned*)d_in[1];
    const float*    W     = (const float*)d_in[2];
    const float*    a_src = (const float*)d_in[3];
    const float*    a_dst = (const float*)d_in[4];
    const float*    Wc1   = (const float*)d_in[5];
    const float*    bc1   = (const float*)d_in[6];
    const float*    Wc2   = (const float*)d_in[7];
    const float*    bc2   = (const float*)d_in[8];
    float* out = (float*)d_out;

    k_pack<<<N_NODES, 128>>>(adj);
    k_gemm<<<dim3(43, 9), 256>>>(x, W, Wc1, bc1);
    k_cond2<<<339, 256>>>(Wc2, bc2);
    k_film<<<dim3(339, M_MECH), 256>>>(a_src, a_dst);
    k_attn<<<dim3((N_NODES + AR - 1) / AR, M_MECH), 256, SMEM_ATTN_BYTES>>>(out);
}